// round 13
// baseline (speedup 1.0000x reference)
#include <cuda_runtime.h>

#define B_    16
#define N_    4096
#define CIN_  64
#define COUT_ 128
#define M_    1024
#define K_    64
#define S_TOT (B_*M_*K_)
#define NPTS  (B_*N_)

typedef unsigned long long ull;

__device__ float  d_pfeat[(size_t)NPTS*64];      // [B*N][64]
__device__ int    d_gidx[S_TOT];
__device__ float  d_gxyz[(size_t)3*S_TOT];       // [3][S]
__device__ float  d_Y[(size_t)64*S_TOT];         // [64][S]
__device__ double d_stats[256];                  // [128..256): BN2 sum/sq
__device__ int    d_cnt[NPTS];
__device__ float  d_G[3*NPTS];
__device__ double d_q[16];                       // Qxx..Qyz, Gxt,Gyt,Gzt
__device__ double d_pstats[320];

__device__ __forceinline__ void fma2(ull &acc, ull a, ull b){
    asm("fma.rn.f32x2 %0, %1, %2, %0;" : "+l"(acc) : "l"(a), "l"(b));
}
__device__ __forceinline__ ull add2(ull a, ull b){
    ull r; asm("add.rn.f32x2 %0, %1, %2;" : "=l"(r) : "l"(a), "l"(b)); return r;
}
__device__ __forceinline__ ull mul2(ull a, ull b){
    ull r; asm("mul.rn.f32x2 %0, %1, %2;" : "=l"(r) : "l"(a), "l"(b)); return r;
}
__device__ __forceinline__ ull pack2(float x, float y){
    ull r; asm("mov.b64 %0, {%1, %2};" : "=l"(r) : "f"(x), "f"(y)); return r;
}
__device__ __forceinline__ float2 unpack2(ull v){
    float2 r; asm("mov.b64 {%0, %1}, %2;" : "=f"(r.x), "=f"(r.y) : "l"(v)); return r;
}

// ---------------- FPS (+ zero all accumulators) ----------------
__global__ void __launch_bounds__(256,1) fps_kernel(const float* __restrict__ points,
                                                    float* __restrict__ cent){
    extern __shared__ ull psm[];
    ull* xx = psm; ull* yy = psm + 2048; ull* zz = psm + 4096;
    __shared__ ull wred[2][8];
    int b = blockIdx.x, tid = threadIdx.x;
    int lane = tid & 31, wid = tid >> 5;
    int gt = b*256 + tid;
    for (int i=gt; i<NPTS; i+=4096) d_cnt[i] = 0;
    for (int i=gt; i<3*NPTS; i+=4096) d_G[i] = 0.f;
    if (gt < 16)  d_q[gt] = 0.0;
    if (gt < 320) d_pstats[gt] = 0.0;
    if (gt >= 320 && gt < 576) d_stats[gt-320] = 0.0;
    const float* pb = points + (size_t)b*3*N_;
    for (int i=tid;i<2048;i+=256){
        xx[i] = pack2(pb[i],        pb[i+2048]);
        yy[i] = pack2(pb[N_+i],     pb[N_+i+2048]);
        zz[i] = pack2(pb[2*N_+i],   pb[2*N_+i+2048]);
    }
    float dist[16];
    #pragma unroll
    for (int j=0;j<16;j++) dist[j] = 1e10f;
    __syncthreads();
    int last = 0;
    float* cb = cent + (size_t)b*M_*3;
    for (int it=0; it<M_; it++){
        int par = it & 1;
        int lp = last & 2047;
        float2 xv = unpack2(xx[lp]), yv = unpack2(yy[lp]), zv = unpack2(zz[lp]);
        float lx = (last < 2048) ? xv.x : xv.y;
        float ly = (last < 2048) ? yv.x : yv.y;
        float lz = (last < 2048) ? zv.x : zv.y;
        if (tid==0){ cb[it*3]=lx; cb[it*3+1]=ly; cb[it*3+2]=lz; }
        ull nlx2 = pack2(-lx,-lx), nly2 = pack2(-ly,-ly), nlz2 = pack2(-lz,-lz);
        unsigned bhi = 0u, bn = 0u;
        #pragma unroll
        for (int j=0;j<8;j++){
            int p = tid + (j<<8);
            ull dx2 = add2(xx[p], nlx2);
            ull dy2 = add2(yy[p], nly2);
            ull dz2 = add2(zz[p], nlz2);
            ull d2 = add2(add2(mul2(dx2,dx2), mul2(dy2,dy2)), mul2(dz2,dz2));
            float2 dd = unpack2(d2);
            float dma = fminf(dist[2*j],   dd.x); dist[2*j]   = dma;
            float dmb = fminf(dist[2*j+1], dd.y); dist[2*j+1] = dmb;
            unsigned ba = __float_as_uint(dma), bb2 = __float_as_uint(dmb);
            if (ba > bhi){ bhi = ba; bn = (unsigned)p; }
            if (bb2 > bhi){ bhi = bb2; bn = (unsigned)(p+2048); }
        }
        unsigned wm = __reduce_max_sync(0xffffffffu, bhi);
        unsigned nc = (bhi == wm) ? bn : 0xffffffffu;
        unsigned wn = __reduce_min_sync(0xffffffffu, nc);
        if (lane==0) wred[par][wid] = ((ull)wm << 32) | wn;
        __syncthreads();
        ull e = (lane < 8) ? wred[par][lane] : 0ull;
        unsigned h2 = (unsigned)(e >> 32), l2 = (unsigned)e;
        unsigned g  = __reduce_max_sync(0xffffffffu, h2);
        unsigned c2 = (h2 == g) ? l2 : 0xffffffffu;
        last = (int)__reduce_min_sync(0xffffffffu, c2);
    }
}

// ---------------- ball query: gxyz + cnt/G + Q + Gtot ----------------
__global__ void __launch_bounds__(512,1) ballq_kernel(const float* __restrict__ points,
                                                      const float* __restrict__ cent){
    extern __shared__ float4 q4[];
    __shared__ float qsm[16][9];
    int b   = blockIdx.x >> 3;
    int seg = blockIdx.x & 7;
    const float* pb = points + (size_t)b*3*N_;
    for (int i=threadIdx.x;i<N_;i+=512)
        q4[i] = make_float4(pb[i], pb[N_+i], pb[2*N_+i], 0.f);
    __syncthreads();
    int wid = threadIdx.x>>5, lane = threadIdx.x&31;
    int pbase = b << 12;
    const float R2 = 0.04f;
    float qv[9] = {0.f,0.f,0.f,0.f,0.f,0.f,0.f,0.f,0.f};
    for (int i=0;i<8;i++){
        int m = seg*128 + wid*8 + i;
        const float* cp = cent + ((size_t)b*M_ + m)*3;
        float cx=cp[0], cy=cp[1], cz=cp[2];
        size_t s0 = ((size_t)b*M_ + m) << 6;
        int* g = d_gidx + s0;
        int cnt = 0, first = -1;
        for (int base=0; base<N_; base+=32){
            int n = base + lane;
            float4 v = q4[n];
            float dx=__fadd_rn(v.x,-cx), dy=__fadd_rn(v.y,-cy), dz=__fadd_rn(v.z,-cz);
            float d2 = __fadd_rn(__fadd_rn(__fmul_rn(dx,dx), __fmul_rn(dy,dy)), __fmul_rn(dz,dz));
            bool within = (d2 <= R2);
            unsigned mask = __ballot_sync(0xffffffffu, within);
            if (mask){
                if (first < 0) first = base + __ffs(mask) - 1;
                int pos = cnt + __popc(mask & ((1u<<lane)-1u));
                if (within && pos < K_){
                    g[pos] = n;
                    d_gxyz[s0 + pos]            = dx;
                    d_gxyz[S_TOT + s0 + pos]    = dy;
                    d_gxyz[2*S_TOT + s0 + pos]  = dz;
                    atomicAdd(&d_cnt[pbase + n], 1);
                    atomicAdd(&d_G[pbase + n],          dx);
                    atomicAdd(&d_G[NPTS + pbase + n],   dy);
                    atomicAdd(&d_G[2*NPTS + pbase + n], dz);
                    qv[0] += dx*dx; qv[1] += dy*dy; qv[2] += dz*dz;
                    qv[3] += dx*dy; qv[4] += dx*dz; qv[5] += dy*dz;
                    qv[6] += dx;    qv[7] += dy;    qv[8] += dz;
                }
                cnt += __popc(mask);
                if (cnt >= K_) break;
            }
        }
        if (cnt < K_){
            float4 fv = q4[first];
            float fx=__fadd_rn(fv.x,-cx), fy=__fadd_rn(fv.y,-cy), fz=__fadd_rn(fv.z,-cz);
            for (int j = cnt + lane; j < K_; j += 32){
                g[j] = first;
                d_gxyz[s0 + j]           = fx;
                d_gxyz[S_TOT + s0 + j]   = fy;
                d_gxyz[2*S_TOT + s0 + j] = fz;
            }
            if (lane == 0){
                int pad = K_ - cnt;
                float pf2 = (float)pad;
                atomicAdd(&d_cnt[pbase + first], pad);
                atomicAdd(&d_G[pbase + first],          pf2*fx);
                atomicAdd(&d_G[NPTS + pbase + first],   pf2*fy);
                atomicAdd(&d_G[2*NPTS + pbase + first], pf2*fz);
                qv[0] += pf2*fx*fx; qv[1] += pf2*fy*fy; qv[2] += pf2*fz*fz;
                qv[3] += pf2*fx*fy; qv[4] += pf2*fx*fz; qv[5] += pf2*fy*fz;
                qv[6] += pf2*fx;    qv[7] += pf2*fy;    qv[8] += pf2*fz;
            }
        }
    }
    #pragma unroll
    for (int q=0;q<9;q++){
        #pragma unroll
        for (int off=16; off; off>>=1)
            qv[q] += __shfl_down_sync(0xffffffffu, qv[q], off);
    }
    if (lane==0){
        #pragma unroll
        for (int q=0;q<9;q++) qsm[wid][q] = qv[q];
    }
    __syncthreads();
    if (threadIdx.x < 9){
        double s = 0.0;
        #pragma unroll
        for (int w=0;w<16;w++) s += (double)qsm[w][threadIdx.x];
        atomicAdd(&d_q[threadIdx.x], s);
    }
}

// ---------------- pfeat + fused BN1 moment partials ----------------
__global__ void __launch_bounds__(256) pfeatstats_kernel(const float* __restrict__ pf,
                                                         const float* __restrict__ W,
                                                         const float* __restrict__ bias){
    extern __shared__ char smem[];
    float (*xs)[128] = (float(*)[128])smem;            // 32KB
    ull   (*wd)[64]  = (ull(*)[64])(smem + 32768);     // 32KB
    int tid = threadIdx.x;
    int g0 = blockIdx.x * 128;
    int b  = g0 >> 12;
    int n0 = g0 & 4095;
    for (int i=tid; i<64*64; i+=256){
        int c = i>>6, o = i&63;
        float w = W[o*67 + 3 + c];
        wd[c][o] = pack2(w, w);
    }
    for (int i=tid; i<64*32; i+=256){
        int c = i>>5, q = i&31;
        *(float4*)&xs[c][q*4] = *(const float4*)(pf + ((size_t)b*64 + c)*N_ + n0 + q*4);
    }
    __syncthreads();
    int lane = tid & 31, wg = tid >> 5;
    int ch0 = wg << 3;
    ull acc[8][2];
    #pragma unroll
    for (int ch=0;ch<8;ch++){ acc[ch][0]=0ull; acc[ch][1]=0ull; }
    for (int c=0;c<64;c++){
        ull x0 = *(const ull*)&xs[c][2*lane];
        ull x1 = *(const ull*)&xs[c][2*lane+64];
        ulonglong2 wv0 = *(const ulonglong2*)&wd[c][ch0];
        ulonglong2 wv1 = *(const ulonglong2*)&wd[c][ch0+2];
        ulonglong2 wv2 = *(const ulonglong2*)&wd[c][ch0+4];
        ulonglong2 wv3 = *(const ulonglong2*)&wd[c][ch0+6];
        fma2(acc[0][0], wv0.x, x0); fma2(acc[0][1], wv0.x, x1);
        fma2(acc[1][0], wv0.y, x0); fma2(acc[1][1], wv0.y, x1);
        fma2(acc[2][0], wv1.x, x0); fma2(acc[2][1], wv1.x, x1);
        fma2(acc[3][0], wv1.y, x0); fma2(acc[3][1], wv1.y, x1);
        fma2(acc[4][0], wv2.x, x0); fma2(acc[4][1], wv2.x, x1);
        fma2(acc[5][0], wv2.y, x0); fma2(acc[5][1], wv2.y, x1);
        fma2(acc[6][0], wv3.x, x0); fma2(acc[6][1], wv3.x, x1);
        fma2(acc[7][0], wv3.y, x0); fma2(acc[7][1], wv3.y, x1);
    }
    __syncthreads();
    float (*ps)[130]  = (float(*)[130])smem;                     // 33280B
    float (*scg)[128] = (float(*)[128])(smem + 40960);           // 2KB
    double (*red)[5][64] = (double(*)[5][64])(smem + 49152);     // 10KB
    #pragma unroll
    for (int ch=0;ch<8;ch++){
        int o = ch0 + ch;
        float bb = bias[o];
        #pragma unroll
        for (int j=0;j<2;j++){
            float2 v = unpack2(acc[ch][j]);
            int sp = 2*lane + 64*j;
            ps[o][sp]   = v.x + bb;
            ps[o][sp+1] = v.y + bb;
        }
    }
    if (tid < 128){
        scg[0][tid] = (float)d_cnt[g0+tid];
        scg[1][tid] = d_G[g0+tid];
    } else {
        int t = tid - 128;
        scg[2][t] = d_G[NPTS + g0 + t];
        scg[3][t] = d_G[2*NPTS + g0 + t];
    }
    __syncthreads();
    float* dst = d_pfeat + (size_t)g0*64;
    for (int i=tid; i<8192; i+=256)
        dst[i] = ps[i&63][i>>6];
    {
        int ch = tid & 63, grp = tid >> 6;
        float a0=0.f,a1=0.f,a2=0.f,a3=0.f,a4=0.f;
        #pragma unroll 8
        for (int k=grp; k<128; k+=4){
            float p = ps[ch][k];
            float cp = scg[0][k]*p;
            a0 += cp;
            a1 = fmaf(cp, p, a1);
            a2 = fmaf(p, scg[1][k], a2);
            a3 = fmaf(p, scg[2][k], a3);
            a4 = fmaf(p, scg[3][k], a4);
        }
        red[grp][0][ch] = (double)a0;
        red[grp][1][ch] = (double)a1;
        red[grp][2][ch] = (double)a2;
        red[grp][3][ch] = (double)a3;
        red[grp][4][ch] = (double)a4;
    }
    __syncthreads();
    for (int i=tid; i<320; i+=256){
        int s = i>>6, c2 = i&63;
        atomicAdd(&d_pstats[i],
                  red[0][s][c2]+red[1][s][c2]+red[2][s][c2]+red[3][s][c2]);
    }
}

// ---------------- gemm2: 4 warps x 16ch x 256 samples; un-dup weights ----------------
__global__ void __launch_bounds__(128) gemm2_kernel(const float* __restrict__ W1,
                                                    const float* __restrict__ W,
                                                    const float* __restrict__ bias,
                                                    const float* __restrict__ g1,
                                                    const float* __restrict__ beta1){
    extern __shared__ char smem[];
    float (*xs)[256] = (float(*)[256])smem;            // 64KB
    float (*ws)[64]  = (float(*)[64])(smem + 65536);   // 16KB
    __shared__ float s_ac[128];
    int tid = threadIdx.x;
    int s0 = blockIdx.x * 256;
    if (tid < 64){
        int i = tid;
        double wx = (double)W1[i*67], wy = (double)W1[i*67+1], wz = (double)W1[i*67+2];
        double S1 = d_pstats[i] + wx*d_q[6] + wy*d_q[7] + wz*d_q[8];
        double S2 = d_pstats[64+i]
                  + 2.0*(wx*d_pstats[128+i] + wy*d_pstats[192+i] + wz*d_pstats[256+i])
                  + wx*wx*d_q[0] + wy*wy*d_q[1] + wz*wz*d_q[2]
                  + 2.0*(wx*wy*d_q[3] + wx*wz*d_q[4] + wy*wz*d_q[5]);
        double mean = S1 * (1.0/(double)S_TOT);
        double var  = S2 * (1.0/(double)S_TOT) - mean*mean;
        float a = (float)((double)g1[i] * rsqrt(var + 1e-5));
        s_ac[i]      = a;
        s_ac[64 + i] = (float)((double)beta1[i] - (double)a*mean);
    }
    for (int i=tid; i<64*64; i+=128){
        int c = i>>6, o = i&63;
        ws[c][o] = W[o*64 + c];
    }
    #pragma unroll
    for (int h=0;h<2;h++){
        int sp = tid + 128*h;
        int s = s0 + sp;
        int idx = d_gidx[s];
        int b = s >> 16;
        const float4* row = (const float4*)(d_pfeat + (((size_t)b*N_ + idx)<<6));
        #pragma unroll
        for (int q=0;q<16;q++){
            float4 v = row[q];
            int c = q*4;
            xs[c][sp]=v.x; xs[c+1][sp]=v.y; xs[c+2][sp]=v.z; xs[c+3][sp]=v.w;
        }
    }
    __syncthreads();
    int lane = tid & 31, wg = tid >> 5;
    int ch0 = wg << 4;
    #pragma unroll
    for (int j=0;j<4;j++){
        int sp = 2*lane + 64*j;
        ull gx2 = *(const ull*)&d_gxyz[s0+sp];
        ull gy2 = *(const ull*)&d_gxyz[S_TOT + s0+sp];
        ull gz2 = *(const ull*)&d_gxyz[2*S_TOT + s0+sp];
        #pragma unroll
        for (int ch=0;ch<16;ch++){
            int o = ch0+ch;
            float wx=W1[o*67], wy=W1[o*67+1], wz=W1[o*67+2];
            float aa=s_ac[o], cc=s_ac[64+o];
            ull y2 = *(const ull*)&xs[o][sp];
            fma2(y2, pack2(wx,wx), gx2);
            fma2(y2, pack2(wy,wy), gy2);
            fma2(y2, pack2(wz,wz), gz2);
            ull t2 = pack2(cc,cc);
            fma2(t2, pack2(aa,aa), y2);
            float2 v = unpack2(t2);
            v.x = fmaxf(v.x, 0.f); v.y = fmaxf(v.y, 0.f);
            *(ull*)&xs[o][sp] = pack2(v.x, v.y);
        }
    }
    __syncthreads();
    ull acc[16][4];
    #pragma unroll
    for (int ch=0;ch<16;ch++){
        #pragma unroll
        for (int j=0;j<4;j++) acc[ch][j]=0ull;
    }
    for (int c=0;c<64;c++){
        ull x0 = *(const ull*)&xs[c][2*lane];
        ull x1 = *(const ull*)&xs[c][2*lane+64];
        ull x2 = *(const ull*)&xs[c][2*lane+128];
        ull x3 = *(const ull*)&xs[c][2*lane+192];
        #pragma unroll
        for (int p=0;p<4;p++){
            float4 wv = *(const float4*)&ws[c][ch0 + 4*p];
            ull w0=pack2(wv.x,wv.x), w1=pack2(wv.y,wv.y), w2=pack2(wv.z,wv.z), w3=pack2(wv.w,wv.w);
            int q = 4*p;
            fma2(acc[q][0],   w0, x0); fma2(acc[q][1],   w0, x1);
            fma2(acc[q][2],   w0, x2); fma2(acc[q][3],   w0, x3);
            fma2(acc[q+1][0], w1, x0); fma2(acc[q+1][1], w1, x1);
            fma2(acc[q+1][2], w1, x2); fma2(acc[q+1][3], w1, x3);
            fma2(acc[q+2][0], w2, x0); fma2(acc[q+2][1], w2, x1);
            fma2(acc[q+2][2], w2, x2); fma2(acc[q+2][3], w2, x3);
            fma2(acc[q+3][0], w3, x0); fma2(acc[q+3][1], w3, x1);
            fma2(acc[q+3][2], w3, x2); fma2(acc[q+3][3], w3, x3);
        }
    }
    #pragma unroll
    for (int ch=0;ch<16;ch++){
        int o = ch0 + ch;
        float bb = bias[o];
        float sm = 0.f, sq = 0.f;
        #pragma unroll
        for (int j=0;j<4;j++){
            float2 v = unpack2(acc[ch][j]);
            v.x += bb; v.y += bb;
            *(float2*)(d_Y + (size_t)o*S_TOT + s0 + 2*lane + 64*j) = v;
            sm += v.x + v.y;
            sq += v.x*v.x + v.y*v.y;
        }
        #pragma unroll
        for (int off=16; off; off>>=1){
            sm += __shfl_down_sync(0xffffffffu, sm, off);
            sq += __shfl_down_sync(0xffffffffu, sq, off);
        }
        if (lane==0){
            atomicAdd(&d_stats[128 + o], (double)sm);
            atomicAdd(&d_stats[192 + o], (double)sq);
        }
    }
}

// ---------------- gemm3: 8 warps x 16ch x 256 samples; un-dup weights ----------------
__global__ void __launch_bounds__(256) gemm3_kernel(const float* __restrict__ W,
                                                    const float* __restrict__ bias,
                                                    const float* __restrict__ g2,
                                                    const float* __restrict__ beta2,
                                                    float* __restrict__ out){
    extern __shared__ char smem[];
    float (*xs)[256] = (float(*)[256])smem;            // 64KB
    float (*ws)[128] = (float(*)[128])(smem + 65536);  // 32KB
    __shared__ float s_ac[128];
    int tid = threadIdx.x;
    int s0 = blockIdx.x * 256;
    if (tid < 64){
        int i = tid;
        double mean = d_stats[128+i] * (1.0/(double)S_TOT);
        double var  = d_stats[192+i] * (1.0/(double)S_TOT) - mean*mean;
        float a = (float)((double)g2[i] * rsqrt(var + 1e-5));
        s_ac[i]      = a;
        s_ac[64 + i] = (float)((double)beta2[i] - (double)a*mean);
    }
    for (int i=tid; i<64*128; i+=256){
        int c = i>>7, o = i&127;
        ws[c][o] = W[o*64 + c];
    }
    __syncthreads();
    for (int i=tid; i<64*64; i+=256){
        int c = i>>6, q = i&63;
        float a  = s_ac[c];
        float cc = s_ac[64 + c];
        float4 y = *(const float4*)(d_Y + (size_t)c*S_TOT + s0 + q*4);
        float4 z;
        z.x = fmaxf(a*y.x + cc, 0.f); z.y = fmaxf(a*y.y + cc, 0.f);
        z.z = fmaxf(a*y.z + cc, 0.f); z.w = fmaxf(a*y.w + cc, 0.f);
        *(float4*)&xs[c][q*4] = z;
    }
    __syncthreads();
    int lane = tid & 31, wg = tid >> 5;
    int ch0 = wg << 4;
    ull acc[16][4];
    #pragma unroll
    for (int ch=0;ch<16;ch++){
        #pragma unroll
        for (int j=0;j<4;j++) acc[ch][j]=0ull;
    }
    for (int c=0;c<64;c++){
        ull x0 = *(const ull*)&xs[c][2*lane];
        ull x1 = *(const ull*)&xs[c][2*lane+64];
        ull x2 = *(const ull*)&xs[c][2*lane+128];
        ull x3 = *(const ull*)&xs[c][2*lane+192];
        #pragma unroll
        for (int p=0;p<4;p++){
            float4 wv = *(const float4*)&ws[c][ch0 + 4*p];
            ull w0=pack2(wv.x,wv.x), w1=pack2(wv.y,wv.y), w2=pack2(wv.z,wv.z), w3=pack2(wv.w,wv.w);
            int q = 4*p;
            fma2(acc[q][0],   w0, x0); fma2(acc[q][1],   w0, x1);
            fma2(acc[q][2],   w0, x2); fma2(acc[q][3],   w0, x3);
            fma2(acc[q+1][0], w1, x0); fma2(acc[q+1][1], w1, x1);
            fma2(acc[q+1][2], w1, x2); fma2(acc[q+1][3], w1, x3);
            fma2(acc[q+2][0], w2, x0); fma2(acc[q+2][1], w2, x1);
            fma2(acc[q+2][2], w2, x2); fma2(acc[q+2][3], w2, x3);
            fma2(acc[q+3][0], w3, x0); fma2(acc[q+3][1], w3, x1);
            fma2(acc[q+3][2], w3, x2); fma2(acc[q+3][3], w3, x3);
        }
    }
    int g0 = s0 >> 6;
    #pragma unroll
    for (int ch=0;ch<16;ch++){
        int o = ch0 + ch;
        #pragma unroll
        for (int j=0;j<4;j++){
            float2 v = unpack2(acc[ch][j]);
            float mx = fmaxf(v.x, v.y);
            #pragma unroll
            for (int off=16; off; off>>=1)
                mx = fmaxf(mx, __shfl_xor_sync(0xffffffffu, mx, off));
            if (lane == 0){
                int grp = g0 + j;
                int b = grp >> 10, m = grp & 1023;
                out[B_*3*M_ + ((size_t)(b*COUT_ + o))*M_ + m] = mx + bias[o];
            }
        }
    }
}

extern "C" void kernel_launch(void* const* d_in, const int* in_sizes, int n_in,
                              void* d_out, int out_size) {
    const float* points = (const float*)d_in[0];
    const float* pf     = (const float*)d_in[1];
    const float* w1 = (const float*)d_in[2];
    const float* b1 = (const float*)d_in[3];
    const float* g1 = (const float*)d_in[4];
    const float* beta1 = (const float*)d_in[5];
    const float* w2 = (const float*)d_in[6];
    const float* b2 = (const float*)d_in[7];
    const float* g2 = (const float*)d_in[8];
    const float* beta2 = (const float*)d_in[9];
    const float* w3 = (const float*)d_in[10];
    const float* b3 = (const float*)d_in[11];
    float* out = (float*)d_out;
    float* cent = out;

    cudaFuncSetAttribute(fps_kernel,        cudaFuncAttributeMaxDynamicSharedMemorySize, 49152);
    cudaFuncSetAttribute(ballq_kernel,      cudaFuncAttributeMaxDynamicSharedMemorySize, 65536);
    cudaFuncSetAttribute(pfeatstats_kernel, cudaFuncAttributeMaxDynamicSharedMemorySize, 65536);
    cudaFuncSetAttribute(gemm2_kernel,      cudaFuncAttributeMaxDynamicSharedMemorySize, 81920);
    cudaFuncSetAttribute(gemm3_kernel,      cudaFuncAttributeMaxDynamicSharedMemorySize, 98304);

    fps_kernel<<<B_, 256, 49152>>>(points, cent);
    ballq_kernel<<<B_*(M_/128), 512, 65536>>>(points, cent);
    pfeatstats_kernel<<<NPTS/128, 256, 65536>>>(pf, w1, b1);
    gemm2_kernel<<<S_TOT/256, 128, 81920>>>(w1, w2, b2, g1, beta1);   // profiled (index 3)
    gemm3_kernel<<<S_TOT/256, 256, 98304>>>(w3, b3, g2, beta2, out);
}

// round 14
// speedup vs baseline: 1.0390x; 1.0390x over previous
#include <cuda_runtime.h>

#define B_    16
#define N_    4096
#define CIN_  64
#define COUT_ 128
#define M_    1024
#define K_    64
#define S_TOT (B_*M_*K_)
#define NPTS  (B_*N_)

typedef unsigned long long ull;

__device__ float  d_pfeat[(size_t)NPTS*64];      // [B*N][64]
__device__ int    d_gidx[S_TOT];
__device__ float  d_gxyz[(size_t)3*S_TOT];       // [3][S]
__device__ float  d_Y[(size_t)64*S_TOT];         // [64][S]
__device__ double d_stats[256];                  // [128..256): BN2 sum/sq
__device__ int    d_cnt[NPTS];
__device__ float  d_G[3*NPTS];
__device__ double d_q[16];                       // Qxx..Qyz, Gxt,Gyt,Gzt
__device__ double d_pstats[320];

__device__ __forceinline__ void fma2(ull &acc, ull a, ull b){
    asm("fma.rn.f32x2 %0, %1, %2, %0;" : "+l"(acc) : "l"(a), "l"(b));
}
__device__ __forceinline__ ull add2(ull a, ull b){
    ull r; asm("add.rn.f32x2 %0, %1, %2;" : "=l"(r) : "l"(a), "l"(b)); return r;
}
__device__ __forceinline__ ull mul2(ull a, ull b){
    ull r; asm("mul.rn.f32x2 %0, %1, %2;" : "=l"(r) : "l"(a), "l"(b)); return r;
}
__device__ __forceinline__ ull pack2(float x, float y){
    ull r; asm("mov.b64 %0, {%1, %2};" : "=l"(r) : "f"(x), "f"(y)); return r;
}
__device__ __forceinline__ float2 unpack2(ull v){
    float2 r; asm("mov.b64 {%0, %1}, %2;" : "=f"(r.x), "=f"(r.y) : "l"(v)); return r;
}

// ---------------- FPS (+ zero all accumulators) ----------------
__global__ void __launch_bounds__(256,1) fps_kernel(const float* __restrict__ points,
                                                    float* __restrict__ cent){
    extern __shared__ ull psm[];
    ull* xx = psm; ull* yy = psm + 2048; ull* zz = psm + 4096;
    __shared__ ull wred[2][8];
    int b = blockIdx.x, tid = threadIdx.x;
    int lane = tid & 31, wid = tid >> 5;
    int gt = b*256 + tid;
    for (int i=gt; i<NPTS; i+=4096) d_cnt[i] = 0;
    for (int i=gt; i<3*NPTS; i+=4096) d_G[i] = 0.f;
    if (gt < 16)  d_q[gt] = 0.0;
    if (gt < 320) d_pstats[gt] = 0.0;
    if (gt >= 320 && gt < 576) d_stats[gt-320] = 0.0;
    const float* pb = points + (size_t)b*3*N_;
    for (int i=tid;i<2048;i+=256){
        xx[i] = pack2(pb[i],        pb[i+2048]);
        yy[i] = pack2(pb[N_+i],     pb[N_+i+2048]);
        zz[i] = pack2(pb[2*N_+i],   pb[2*N_+i+2048]);
    }
    float dist[16];
    #pragma unroll
    for (int j=0;j<16;j++) dist[j] = 1e10f;
    __syncthreads();
    int last = 0;
    float* cb = cent + (size_t)b*M_*3;
    for (int it=0; it<M_; it++){
        int par = it & 1;
        int lp = last & 2047;
        float2 xv = unpack2(xx[lp]), yv = unpack2(yy[lp]), zv = unpack2(zz[lp]);
        float lx = (last < 2048) ? xv.x : xv.y;
        float ly = (last < 2048) ? yv.x : yv.y;
        float lz = (last < 2048) ? zv.x : zv.y;
        if (tid==0){ cb[it*3]=lx; cb[it*3+1]=ly; cb[it*3+2]=lz; }
        ull nlx2 = pack2(-lx,-lx), nly2 = pack2(-ly,-ly), nlz2 = pack2(-lz,-lz);
        unsigned bhi = 0u, bn = 0u;
        #pragma unroll
        for (int j=0;j<8;j++){
            int p = tid + (j<<8);
            ull dx2 = add2(xx[p], nlx2);
            ull dy2 = add2(yy[p], nly2);
            ull dz2 = add2(zz[p], nlz2);
            ull d2 = add2(add2(mul2(dx2,dx2), mul2(dy2,dy2)), mul2(dz2,dz2));
            float2 dd = unpack2(d2);
            float dma = fminf(dist[2*j],   dd.x); dist[2*j]   = dma;
            float dmb = fminf(dist[2*j+1], dd.y); dist[2*j+1] = dmb;
            unsigned ba = __float_as_uint(dma), bb2 = __float_as_uint(dmb);
            if (ba > bhi){ bhi = ba; bn = (unsigned)p; }
            if (bb2 > bhi){ bhi = bb2; bn = (unsigned)(p+2048); }
        }
        unsigned wm = __reduce_max_sync(0xffffffffu, bhi);
        unsigned nc = (bhi == wm) ? bn : 0xffffffffu;
        unsigned wn = __reduce_min_sync(0xffffffffu, nc);
        if (lane==0) wred[par][wid] = ((ull)wm << 32) | wn;
        __syncthreads();
        ull e = (lane < 8) ? wred[par][lane] : 0ull;
        unsigned h2 = (unsigned)(e >> 32), l2 = (unsigned)e;
        unsigned g  = __reduce_max_sync(0xffffffffu, h2);
        unsigned c2 = (h2 == g) ? l2 : 0xffffffffu;
        last = (int)__reduce_min_sync(0xffffffffu, c2);
    }
}

// ---------------- ball query: gxyz + cnt/G + Q + Gtot ----------------
__global__ void __launch_bounds__(512,1) ballq_kernel(const float* __restrict__ points,
                                                      const float* __restrict__ cent){
    extern __shared__ float4 q4[];
    __shared__ float qsm[16][9];
    int b   = blockIdx.x >> 3;
    int seg = blockIdx.x & 7;
    const float* pb = points + (size_t)b*3*N_;
    for (int i=threadIdx.x;i<N_;i+=512)
        q4[i] = make_float4(pb[i], pb[N_+i], pb[2*N_+i], 0.f);
    __syncthreads();
    int wid = threadIdx.x>>5, lane = threadIdx.x&31;
    int pbase = b << 12;
    const float R2 = 0.04f;
    float qv[9] = {0.f,0.f,0.f,0.f,0.f,0.f,0.f,0.f,0.f};
    for (int i=0;i<8;i++){
        int m = seg*128 + wid*8 + i;
        const float* cp = cent + ((size_t)b*M_ + m)*3;
        float cx=cp[0], cy=cp[1], cz=cp[2];
        size_t s0 = ((size_t)b*M_ + m) << 6;
        int* g = d_gidx + s0;
        int cnt = 0, first = -1;
        for (int base=0; base<N_; base+=32){
            int n = base + lane;
            float4 v = q4[n];
            float dx=__fadd_rn(v.x,-cx), dy=__fadd_rn(v.y,-cy), dz=__fadd_rn(v.z,-cz);
            float d2 = __fadd_rn(__fadd_rn(__fmul_rn(dx,dx), __fmul_rn(dy,dy)), __fmul_rn(dz,dz));
            bool within = (d2 <= R2);
            unsigned mask = __ballot_sync(0xffffffffu, within);
            if (mask){
                if (first < 0) first = base + __ffs(mask) - 1;
                int pos = cnt + __popc(mask & ((1u<<lane)-1u));
                if (within && pos < K_){
                    g[pos] = n;
                    d_gxyz[s0 + pos]            = dx;
                    d_gxyz[S_TOT + s0 + pos]    = dy;
                    d_gxyz[2*S_TOT + s0 + pos]  = dz;
                    atomicAdd(&d_cnt[pbase + n], 1);
                    atomicAdd(&d_G[pbase + n],          dx);
                    atomicAdd(&d_G[NPTS + pbase + n],   dy);
                    atomicAdd(&d_G[2*NPTS + pbase + n], dz);
                    qv[0] += dx*dx; qv[1] += dy*dy; qv[2] += dz*dz;
                    qv[3] += dx*dy; qv[4] += dx*dz; qv[5] += dy*dz;
                    qv[6] += dx;    qv[7] += dy;    qv[8] += dz;
                }
                cnt += __popc(mask);
                if (cnt >= K_) break;
            }
        }
        if (cnt < K_){
            float4 fv = q4[first];
            float fx=__fadd_rn(fv.x,-cx), fy=__fadd_rn(fv.y,-cy), fz=__fadd_rn(fv.z,-cz);
            for (int j = cnt + lane; j < K_; j += 32){
                g[j] = first;
                d_gxyz[s0 + j]           = fx;
                d_gxyz[S_TOT + s0 + j]   = fy;
                d_gxyz[2*S_TOT + s0 + j] = fz;
            }
            if (lane == 0){
                int pad = K_ - cnt;
                float pf2 = (float)pad;
                atomicAdd(&d_cnt[pbase + first], pad);
                atomicAdd(&d_G[pbase + first],          pf2*fx);
                atomicAdd(&d_G[NPTS + pbase + first],   pf2*fy);
                atomicAdd(&d_G[2*NPTS + pbase + first], pf2*fz);
                qv[0] += pf2*fx*fx; qv[1] += pf2*fy*fy; qv[2] += pf2*fz*fz;
                qv[3] += pf2*fx*fy; qv[4] += pf2*fx*fz; qv[5] += pf2*fy*fz;
                qv[6] += pf2*fx;    qv[7] += pf2*fy;    qv[8] += pf2*fz;
            }
        }
    }
    #pragma unroll
    for (int q=0;q<9;q++){
        #pragma unroll
        for (int off=16; off; off>>=1)
            qv[q] += __shfl_down_sync(0xffffffffu, qv[q], off);
    }
    if (lane==0){
        #pragma unroll
        for (int q=0;q<9;q++) qsm[wid][q] = qv[q];
    }
    __syncthreads();
    if (threadIdx.x < 9){
        double s = 0.0;
        #pragma unroll
        for (int w=0;w<16;w++) s += (double)qsm[w][threadIdx.x];
        atomicAdd(&d_q[threadIdx.x], s);
    }
}

// ---------------- pfeat + fused BN1 moment partials ----------------
__global__ void __launch_bounds__(256) pfeatstats_kernel(const float* __restrict__ pf,
                                                         const float* __restrict__ W,
                                                         const float* __restrict__ bias){
    extern __shared__ char smem[];
    float (*xs)[128] = (float(*)[128])smem;            // 32KB
    ull   (*wd)[64]  = (ull(*)[64])(smem + 32768);     // 32KB
    int tid = threadIdx.x;
    int g0 = blockIdx.x * 128;
    int b  = g0 >> 12;
    int n0 = g0 & 4095;
    for (int i=tid; i<64*64; i+=256){
        int c = i>>6, o = i&63;
        float w = W[o*67 + 3 + c];
        wd[c][o] = pack2(w, w);
    }
    for (int i=tid; i<64*32; i+=256){
        int c = i>>5, q = i&31;
        *(float4*)&xs[c][q*4] = *(const float4*)(pf + ((size_t)b*64 + c)*N_ + n0 + q*4);
    }
    __syncthreads();
    int lane = tid & 31, wg = tid >> 5;
    int ch0 = wg << 3;
    ull acc[8][2];
    #pragma unroll
    for (int ch=0;ch<8;ch++){ acc[ch][0]=0ull; acc[ch][1]=0ull; }
    for (int c=0;c<64;c++){
        ull x0 = *(const ull*)&xs[c][2*lane];
        ull x1 = *(const ull*)&xs[c][2*lane+64];
        ulonglong2 wv0 = *(const ulonglong2*)&wd[c][ch0];
        ulonglong2 wv1 = *(const ulonglong2*)&wd[c][ch0+2];
        ulonglong2 wv2 = *(const ulonglong2*)&wd[c][ch0+4];
        ulonglong2 wv3 = *(const ulonglong2*)&wd[c][ch0+6];
        fma2(acc[0][0], wv0.x, x0); fma2(acc[0][1], wv0.x, x1);
        fma2(acc[1][0], wv0.y, x0); fma2(acc[1][1], wv0.y, x1);
        fma2(acc[2][0], wv1.x, x0); fma2(acc[2][1], wv1.x, x1);
        fma2(acc[3][0], wv1.y, x0); fma2(acc[3][1], wv1.y, x1);
        fma2(acc[4][0], wv2.x, x0); fma2(acc[4][1], wv2.x, x1);
        fma2(acc[5][0], wv2.y, x0); fma2(acc[5][1], wv2.y, x1);
        fma2(acc[6][0], wv3.x, x0); fma2(acc[6][1], wv3.x, x1);
        fma2(acc[7][0], wv3.y, x0); fma2(acc[7][1], wv3.y, x1);
    }
    __syncthreads();
    float (*ps)[130]  = (float(*)[130])smem;                     // 33280B
    float (*scg)[128] = (float(*)[128])(smem + 40960);           // 2KB
    double (*red)[5][64] = (double(*)[5][64])(smem + 49152);     // 10KB
    #pragma unroll
    for (int ch=0;ch<8;ch++){
        int o = ch0 + ch;
        float bb = bias[o];
        #pragma unroll
        for (int j=0;j<2;j++){
            float2 v = unpack2(acc[ch][j]);
            int sp = 2*lane + 64*j;
            ps[o][sp]   = v.x + bb;
            ps[o][sp+1] = v.y + bb;
        }
    }
    if (tid < 128){
        scg[0][tid] = (float)d_cnt[g0+tid];
        scg[1][tid] = d_G[g0+tid];
    } else {
        int t = tid - 128;
        scg[2][t] = d_G[NPTS + g0 + t];
        scg[3][t] = d_G[2*NPTS + g0 + t];
    }
    __syncthreads();
    float* dst = d_pfeat + (size_t)g0*64;
    for (int i=tid; i<8192; i+=256)
        dst[i] = ps[i&63][i>>6];
    {
        int ch = tid & 63, grp = tid >> 6;
        float a0=0.f,a1=0.f,a2=0.f,a3=0.f,a4=0.f;
        #pragma unroll 8
        for (int k=grp; k<128; k+=4){
            float p = ps[ch][k];
            float cp = scg[0][k]*p;
            a0 += cp;
            a1 = fmaf(cp, p, a1);
            a2 = fmaf(p, scg[1][k], a2);
            a3 = fmaf(p, scg[2][k], a3);
            a4 = fmaf(p, scg[3][k], a4);
        }
        red[grp][0][ch] = (double)a0;
        red[grp][1][ch] = (double)a1;
        red[grp][2][ch] = (double)a2;
        red[grp][3][ch] = (double)a3;
        red[grp][4][ch] = (double)a4;
    }
    __syncthreads();
    for (int i=tid; i<320; i+=256){
        int s = i>>6, c2 = i&63;
        atomicAdd(&d_pstats[i],
                  red[0][s][c2]+red[1][s][c2]+red[2][s][c2]+red[3][s][c2]);
    }
}

// ---------------- gemm2: 8 warps; warp = 16ch x 128-sample half; un-dup weights ----------------
__global__ void __launch_bounds__(256) gemm2_kernel(const float* __restrict__ W1,
                                                    const float* __restrict__ W,
                                                    const float* __restrict__ bias,
                                                    const float* __restrict__ g1,
                                                    const float* __restrict__ beta1){
    extern __shared__ char smem[];
    float (*xs)[256] = (float(*)[256])smem;            // 64KB
    float (*ws)[64]  = (float(*)[64])(smem + 65536);   // 16KB
    __shared__ float s_ac[128];
    int tid = threadIdx.x;
    int s0 = blockIdx.x * 256;
    if (tid < 64){
        int i = tid;
        double wx = (double)W1[i*67], wy = (double)W1[i*67+1], wz = (double)W1[i*67+2];
        double S1 = d_pstats[i] + wx*d_q[6] + wy*d_q[7] + wz*d_q[8];
        double S2 = d_pstats[64+i]
                  + 2.0*(wx*d_pstats[128+i] + wy*d_pstats[192+i] + wz*d_pstats[256+i])
                  + wx*wx*d_q[0] + wy*wy*d_q[1] + wz*wz*d_q[2]
                  + 2.0*(wx*wy*d_q[3] + wx*wz*d_q[4] + wy*wz*d_q[5]);
        double mean = S1 * (1.0/(double)S_TOT);
        double var  = S2 * (1.0/(double)S_TOT) - mean*mean;
        float a = (float)((double)g1[i] * rsqrt(var + 1e-5));
        s_ac[i]      = a;
        s_ac[64 + i] = (float)((double)beta1[i] - (double)a*mean);
    }
    for (int i=tid; i<64*64; i+=256){
        int c = i>>6, o = i&63;
        ws[c][o] = W[o*64 + c];
    }
    {
        int s = s0 + tid;
        int idx = d_gidx[s];
        int b = s >> 16;
        const float4* row = (const float4*)(d_pfeat + (((size_t)b*N_ + idx)<<6));
        #pragma unroll
        for (int q=0;q<16;q++){
            float4 v = row[q];
            int c = q*4;
            xs[c][tid]=v.x; xs[c+1][tid]=v.y; xs[c+2][tid]=v.z; xs[c+3][tid]=v.w;
        }
    }
    __syncthreads();
    int lane = tid & 31, wg = tid >> 5;
    int ch0  = (wg & 3) << 4;        // 16 channels
    int half = (wg >> 2) << 7;       // sample-half offset (0 or 128)
    // transform: this warp transforms its 16 channels over its 128 samples
    #pragma unroll
    for (int j=0;j<2;j++){
        int sp = half + 2*lane + 64*j;
        ull gx2 = *(const ull*)&d_gxyz[s0+sp];
        ull gy2 = *(const ull*)&d_gxyz[S_TOT + s0+sp];
        ull gz2 = *(const ull*)&d_gxyz[2*S_TOT + s0+sp];
        #pragma unroll
        for (int ch=0;ch<16;ch++){
            int o = ch0+ch;
            float wx=W1[o*67], wy=W1[o*67+1], wz=W1[o*67+2];
            float aa=s_ac[o], cc=s_ac[64+o];
            ull y2 = *(const ull*)&xs[o][sp];
            fma2(y2, pack2(wx,wx), gx2);
            fma2(y2, pack2(wy,wy), gy2);
            fma2(y2, pack2(wz,wz), gz2);
            ull t2 = pack2(cc,cc);
            fma2(t2, pack2(aa,aa), y2);
            float2 v = unpack2(t2);
            v.x = fmaxf(v.x, 0.f); v.y = fmaxf(v.y, 0.f);
            *(ull*)&xs[o][sp] = pack2(v.x, v.y);
        }
    }
    __syncthreads();
    ull acc[16][2];
    #pragma unroll
    for (int ch=0;ch<16;ch++){ acc[ch][0]=0ull; acc[ch][1]=0ull; }
    for (int c=0;c<64;c++){
        ull x0 = *(const ull*)&xs[c][half + 2*lane];
        ull x1 = *(const ull*)&xs[c][half + 2*lane + 64];
        #pragma unroll
        for (int p=0;p<4;p++){
            float4 wv = *(const float4*)&ws[c][ch0 + 4*p];
            ull w0=pack2(wv.x,wv.x), w1=pack2(wv.y,wv.y), w2=pack2(wv.z,wv.z), w3=pack2(wv.w,wv.w);
            int q = 4*p;
            fma2(acc[q][0],   w0, x0); fma2(acc[q][1],   w0, x1);
            fma2(acc[q+1][0], w1, x0); fma2(acc[q+1][1], w1, x1);
            fma2(acc[q+2][0], w2, x0); fma2(acc[q+2][1], w2, x1);
            fma2(acc[q+3][0], w3, x0); fma2(acc[q+3][1], w3, x1);
        }
    }
    #pragma unroll
    for (int ch=0;ch<16;ch++){
        int o = ch0 + ch;
        float bb = bias[o];
        float sm = 0.f, sq = 0.f;
        #pragma unroll
        for (int j=0;j<2;j++){
            float2 v = unpack2(acc[ch][j]);
            v.x += bb; v.y += bb;
            *(float2*)(d_Y + (size_t)o*S_TOT + s0 + half + 2*lane + 64*j) = v;
            sm += v.x + v.y;
            sq += v.x*v.x + v.y*v.y;
        }
        #pragma unroll
        for (int off=16; off; off>>=1){
            sm += __shfl_down_sync(0xffffffffu, sm, off);
            sq += __shfl_down_sync(0xffffffffu, sq, off);
        }
        if (lane==0){
            atomicAdd(&d_stats[128 + o], (double)sm);
            atomicAdd(&d_stats[192 + o], (double)sq);
        }
    }
}

// ---------------- gemm3: R12 version (128-sample tile, un-dup weights, acc[16][2]) ----------------
__global__ void __launch_bounds__(256) gemm3_kernel(const float* __restrict__ W,
                                                    const float* __restrict__ bias,
                                                    const float* __restrict__ g2,
                                                    const float* __restrict__ beta2,
                                                    float* __restrict__ out){
    extern __shared__ char smem[];
    float (*xs)[128] = (float(*)[128])smem;            // 32KB
    float (*ws)[128] = (float(*)[128])(smem + 32768);  // 32KB
    __shared__ float s_ac[128];
    int tid = threadIdx.x;
    int s0 = blockIdx.x * 128;
    if (tid < 64){
        int i = tid;
        double mean = d_stats[128+i] * (1.0/(double)S_TOT);
        double var  = d_stats[192+i] * (1.0/(double)S_TOT) - mean*mean;
        float a = (float)((double)g2[i] * rsqrt(var + 1e-5));
        s_ac[i]      = a;
        s_ac[64 + i] = (float)((double)beta2[i] - (double)a*mean);
    }
    for (int i=tid; i<64*128; i+=256){
        int c = i>>7, o = i&127;
        ws[c][o] = W[o*64 + c];
    }
    __syncthreads();
    for (int i=tid; i<64*32; i+=256){
        int c = i>>5, q = i&31;
        float a  = s_ac[c];
        float cc = s_ac[64 + c];
        float4 y = *(const float4*)(d_Y + (size_t)c*S_TOT + s0 + q*4);
        float4 z;
        z.x = fmaxf(a*y.x + cc, 0.f); z.y = fmaxf(a*y.y + cc, 0.f);
        z.z = fmaxf(a*y.z + cc, 0.f); z.w = fmaxf(a*y.w + cc, 0.f);
        *(float4*)&xs[c][q*4] = z;
    }
    __syncthreads();
    int lane = tid & 31, wg = tid >> 5;
    int ch0 = wg << 4;
    ull acc[16][2];
    #pragma unroll
    for (int ch=0;ch<16;ch++){ acc[ch][0]=0ull; acc[ch][1]=0ull; }
    for (int c=0;c<64;c++){
        ull x0 = *(const ull*)&xs[c][2*lane];
        ull x1 = *(const ull*)&xs[c][2*lane+64];
        #pragma unroll
        for (int p=0;p<4;p++){
            float4 wv = *(const float4*)&ws[c][ch0 + 4*p];
            ull w0=pack2(wv.x,wv.x), w1=pack2(wv.y,wv.y), w2=pack2(wv.z,wv.z), w3=pack2(wv.w,wv.w);
            int q = 4*p;
            fma2(acc[q][0],   w0, x0); fma2(acc[q][1],   w0, x1);
            fma2(acc[q+1][0], w1, x0); fma2(acc[q+1][1], w1, x1);
            fma2(acc[q+2][0], w2, x0); fma2(acc[q+2][1], w2, x1);
            fma2(acc[q+3][0], w3, x0); fma2(acc[q+3][1], w3, x1);
        }
    }
    int g0 = s0 >> 6;
    #pragma unroll
    for (int ch=0;ch<16;ch++){
        int o = ch0 + ch;
        #pragma unroll
        for (int j=0;j<2;j++){
            float2 v = unpack2(acc[ch][j]);
            float mx = fmaxf(v.x, v.y);
            #pragma unroll
            for (int off=16; off; off>>=1)
                mx = fmaxf(mx, __shfl_xor_sync(0xffffffffu, mx, off));
            if (lane == 0){
                int grp = g0 + j;
                int b = grp >> 10, m = grp & 1023;
                out[B_*3*M_ + ((size_t)(b*COUT_ + o))*M_ + m] = mx + bias[o];
            }
        }
    }
}

extern "C" void kernel_launch(void* const* d_in, const int* in_sizes, int n_in,
                              void* d_out, int out_size) {
    const float* points = (const float*)d_in[0];
    const float* pf     = (const float*)d_in[1];
    const float* w1 = (const float*)d_in[2];
    const float* b1 = (const float*)d_in[3];
    const float* g1 = (const float*)d_in[4];
    const float* beta1 = (const float*)d_in[5];
    const float* w2 = (const float*)d_in[6];
    const float* b2 = (const float*)d_in[7];
    const float* g2 = (const float*)d_in[8];
    const float* beta2 = (const float*)d_in[9];
    const float* w3 = (const float*)d_in[10];
    const float* b3 = (const float*)d_in[11];
    float* out = (float*)d_out;
    float* cent = out;

    cudaFuncSetAttribute(fps_kernel,        cudaFuncAttributeMaxDynamicSharedMemorySize, 49152);
    cudaFuncSetAttribute(ballq_kernel,      cudaFuncAttributeMaxDynamicSharedMemorySize, 65536);
    cudaFuncSetAttribute(pfeatstats_kernel, cudaFuncAttributeMaxDynamicSharedMemorySize, 65536);
    cudaFuncSetAttribute(gemm2_kernel,      cudaFuncAttributeMaxDynamicSharedMemorySize, 81920);
    cudaFuncSetAttribute(gemm3_kernel,      cudaFuncAttributeMaxDynamicSharedMemorySize, 65536);

    fps_kernel<<<B_, 256, 49152>>>(points, cent);
    ballq_kernel<<<B_*(M_/128), 512, 65536>>>(points, cent);
    pfeatstats_kernel<<<NPTS/128, 256, 65536>>>(pf, w1, b1);
    gemm2_kernel<<<S_TOT/256, 256, 81920>>>(w1, w2, b2, g1, beta1);   // profiled (index 3)
    gemm3_kernel<<<S_TOT/128, 256, 65536>>>(w3, b3, g2, beta2, out);
}